// round 8
// baseline (speedup 1.0000x reference)
#include <cuda_runtime.h>
#include <cuda_bf16.h>
#include <cstdint>

typedef unsigned long long ull;

#define M_MODELS 3
#define B_IMG    16
#define N_BOX    512
#define K_TOT    (M_MODELS * N_BOX)   // 1536
#define PAD      2048
#define NUM_CLS  12
#define CAP      256                  // fast-path bucket capacity
#define W_MAX    4                    // CAP/64 mask words per row
#define KW_MAX   24                   // keep words (covers fallback up to 1536)

// -------- dynamic smem layout (bytes) --------
#define OFF_POOL 0                                   // masks 12*CAP*W_MAX*8 = 98304 (unioned with sort key 16384)
#define OFF_BBX  98304                               // float4[1536] bucket-ordered boxes
#define OFF_BAR  (OFF_BBX + K_TOT * 16)              // float [1536] areas
#define OFF_BSC  (OFF_BAR + K_TOT * 4)               // float [1536] scores (bucket order)
#define OFF_SLAB (OFF_BSC + K_TOT * 4)               // short [1536] sorted labels
#define OFF_SIDX (OFF_SLAB + K_TOT * 2)              // short [1536] bucket->rank
#define OFF_KEEP (OFF_SIDX + K_TOT * 2)              // ull [12*KW_MAX]
#define SMEM_TOTAL (OFF_KEEP + NUM_CLS * KW_MAX * 8) // 143616 B

__device__ __forceinline__ void cswap(ull& x, ull& y, bool up) {
    if ((x > y) == up) { ull t = x; x = y; y = t; }
}

__device__ __forceinline__ ull shfl_stage(ull v, int e, unsigned j, unsigned ks) {
    const ull  o     = __shfl_xor_sync(0xffffffffu, v, j);
    const bool up    = ((e & ks) == 0);
    const bool lower = ((e & j) == 0);
    return ((v < o) == (lower == up)) ? v : o;
}

// division-free exact IoU>0.5 test: 0.5*d is exact in fp32
__device__ __forceinline__ bool iou_gt(const float4 bi, const float ai,
                                       const float4 bj, const float aj) {
    const float iw = fmaxf(fminf(bi.z, bj.z) - fmaxf(bi.x, bj.x), 0.0f);
    const float ih = fmaxf(fminf(bi.w, bj.w) - fmaxf(bi.y, bj.y), 0.0f);
    const float inter = iw * ih;
    const float uni   = ai + aj - inter;
    return inter > 0.5f * fmaxf(uni, 1e-9f);
}

// =============================================================================
// ONE kernel per image: sort -> bucket -> gather(SMEM) -> matrix -> greedy -> out
// =============================================================================
__global__ __launch_bounds__(1024)
void k_all(const float* __restrict__ boxes, const float* __restrict__ scores,
           const int* __restrict__ labels, const float* __restrict__ weights,
           float* __restrict__ out) {
    extern __shared__ char dyn[];
    ull*    key   = (ull*)   (dyn + OFF_POOL);   // phase 1 only
    ull*    pool  = (ull*)   (dyn + OFF_POOL);   // phase 4+ (clobbers key)
    float4* bbx   = (float4*)(dyn + OFF_BBX);
    float*  bar   = (float*) (dyn + OFF_BAR);
    float*  bsc   = (float*) (dyn + OFF_BSC);
    short*  slab  = (short*) (dyn + OFF_SLAB);
    short*  sidx  = (short*) (dyn + OFF_SIDX);
    ull*    keep  = (ull*)   (dyn + OFF_KEEP);

    __shared__ int soff[NUM_CLS], scnt[NUM_CLS];

    const int b    = blockIdx.x;
    const int tid  = threadIdx.x;
    const int warp = tid >> 5, lane = tid & 31;
    const int eA   = (warp << 6) | lane;
    const int eB   = eA | 32;

    const float w0 = weights[0], w1 = weights[1], w2 = weights[2];

    // ---------------- phase 1: bitonic sort of (score desc, idx asc) ----------
    auto mkkey = [&](int s) -> ull {
        if (s >= K_TOT) return ~0ull;
        const int m = s >> 9, n = s & (N_BOX - 1);
        const float wm = (m == 0) ? w0 : ((m == 1) ? w1 : w2);
        const float sc = scores[(m * B_IMG + b) * N_BOX + n] * wm;
        return ((ull)(~__float_as_uint(sc)) << 32) | (unsigned)s;
    };
    ull a = mkkey(eA);
    ull c = mkkey(eB);

    #pragma unroll
    for (int kb = 1; kb <= 6; kb++) {
        const unsigned ks = 1u << kb;
        if (ks == 64) cswap(a, c, ((eA & 64) == 0));
        const unsigned jstart = (ks == 64) ? 16u : (ks >> 1);
        #pragma unroll
        for (unsigned j = jstart; j >= 1; j >>= 1) {
            a = shfl_stage(a, eA, j, ks);
            c = shfl_stage(c, eB, j, ks);
        }
    }
    key[eA] = a;
    key[eB] = c;

    #pragma unroll
    for (unsigned ks = 128; ks <= PAD; ks <<= 1) {
        for (unsigned j = ks >> 1; j >= 64; j >>= 1) {
            __syncthreads();
            const unsigned i = ((tid & ~(j - 1)) << 1) | (tid & (j - 1));
            const unsigned p = i | j;
            const ull x = key[i];
            const ull y = key[p];
            const bool up = ((i & ks) == 0);
            if ((x > y) == up) { key[i] = y; key[p] = x; }
        }
        __syncthreads();
        a = key[eA]; c = key[eB];
        cswap(a, c, ((eA & ks) == 0));
        #pragma unroll
        for (unsigned j = 16; j >= 1; j >>= 1) {
            a = shfl_stage(a, eA, j, ks);
            c = shfl_stage(c, eB, j, ks);
        }
        key[eA] = a; key[eB] = c;
    }
    __syncthreads();

    // ---------------- phase 2: sorted labels ---------------------------------
    for (int r = tid; r < K_TOT; r += 1024) {
        const int e = (int)(key[r] & 0xffffffffu);
        const int m = e >> 9, n = e & (N_BOX - 1);
        slab[r] = (short)labels[((size_t)m * B_IMG + b) * N_BOX + n];
    }
    __syncthreads();

    // ---------------- phase 3: per-class stable compaction (warp l = class l) -
    if (warp < NUM_CLS) {
        int cnt = 0;
        for (int base = 0; base < K_TOT; base += 32) {
            const bool m = (slab[base + lane] == (short)warp);
            cnt += __popc(__ballot_sync(0xffffffffu, m));
        }
        if (lane == 0) scnt[warp] = cnt;
    }
    __syncthreads();
    if (tid == 0) {
        int acc = 0;
        #pragma unroll
        for (int l = 0; l < NUM_CLS; l++) { soff[l] = acc; acc += scnt[l]; }
    }
    __syncthreads();
    if (warp < NUM_CLS) {
        const int off = soff[warp];
        int cnt = 0;
        for (int base = 0; base < K_TOT; base += 32) {
            const bool m = (slab[base + lane] == (short)warp);
            const unsigned bal = __ballot_sync(0xffffffffu, m);
            if (m) {
                const int pos = cnt + __popc(bal & ((1u << lane) - 1u));
                sidx[off + pos] = (short)(base + lane);
            }
            cnt += __popc(bal);
        }
    }
    __syncthreads();

    // ---------------- phase 4: bucket-ordered gather into SMEM ----------------
    // (score comes straight from the sort key; only boxes hit global)
    for (int e = tid; e < K_TOT; e += 1024) {
        const int rank = sidx[e];
        const ull kk   = key[rank];
        const int  src = (int)(kk & 0xffffffffu);
        const int  m   = src >> 9, n = src & (N_BOX - 1);
        const float4 bb =
            *(const float4*)&boxes[(((size_t)m * B_IMG + b) * N_BOX + n) * 4];
        bbx[e] = bb;
        bar[e] = (bb.z - bb.x) * (bb.w - bb.y);
        bsc[e] = __uint_as_float(~(unsigned)(kk >> 32));
    }
    __syncthreads();   // key dead from here; pool aliases it

    // ---------------- phase 5: suppression matrices (all 32 warps) ------------
    // bucket = warp % 12; stripes = warps assigned to that bucket
    {
        const int bkt = warp % NUM_CLS;
        const int str = warp / NUM_CLS;
        const int nst = 2 + (bkt < (32 - 2 * NUM_CLS));   // 3 for bkt<8, else 2
        const int off = soff[bkt];
        const int cnt = scnt[bkt];
        if (cnt <= CAP) {
            const int W = (cnt + 63) >> 6;
            ull* mrow = pool + (size_t)bkt * CAP * W_MAX;
            for (int r = str; r < cnt; r += nst) {
                const float4 bi = bbx[off + r];
                const float  ai = bar[off + r];
                for (int w = r >> 6; w < W; w++) {
                    const int j0 = w * 64 + lane;
                    const int j1 = j0 + 32;
                    bool p0 = false, p1 = false;
                    if (j0 > r && j0 < cnt) p0 = iou_gt(bi, ai, bbx[off + j0], bar[off + j0]);
                    if (j1 > r && j1 < cnt) p1 = iou_gt(bi, ai, bbx[off + j1], bar[off + j1]);
                    const unsigned lo = __ballot_sync(0xffffffffu, p0);
                    const unsigned hi = __ballot_sync(0xffffffffu, p1);
                    if (lane == 0)
                        mrow[r * W_MAX + w] = ((ull)hi << 32) | lo;
                }
            }
        }
    }
    __syncthreads();

    // ---------------- phase 6: greedy chase, 12 warps in parallel --------------
    if (warp < NUM_CLS) {
        const int bkt = warp;
        const int off = soff[bkt];
        const int cnt = scnt[bkt];
        if (cnt > 0 && cnt <= CAP) {
            const int W = (cnt + 63) >> 6;
            const ull* mrow = pool + (size_t)bkt * CAP * W_MAX;
            ull removed = 0ull;
            for (int i = 0; i < cnt; i++) {
                const int cc = i >> 6;
                const ull wc = __shfl_sync(0xffffffffu, removed, cc);
                if (!((wc >> (i & 63)) & 1ull)) {
                    if (lane >= cc && lane < W)
                        removed |= mrow[i * W_MAX + lane];
                }
            }
            if (lane < W) keep[bkt * KW_MAX + lane] = ~removed;
        } else if (cnt > CAP) {
            // fallback: warp-serial greedy straight from SMEM boxes
            short* klist = (short*)(pool + (size_t)bkt * CAP * W_MAX);
            for (int w = lane; w < KW_MAX; w += 32) keep[bkt * KW_MAX + w] = 0ull;
            __syncwarp();
            int nk = 0;
            for (int cix = 0; cix < cnt; cix++) {
                const float4 bc = bbx[off + cix];
                const float  ac = bar[off + cix];
                bool sup = false;
                for (int k = lane; k < nk; k += 32) {
                    const int rk = klist[k];
                    if (iou_gt(bc, ac, bbx[off + rk], bar[off + rk])) { sup = true; break; }
                }
                sup = (__ballot_sync(0xffffffffu, sup) != 0u);
                if (!sup) {
                    if (lane == 0) {
                        klist[nk] = (short)cix;
                        keep[bkt * KW_MAX + (cix >> 6)] |= 1ull << (cix & 63);
                    }
                    nk++;
                }
                __syncwarp();
            }
        }
    }
    __syncthreads();

    // ---------------- phase 7: output ------------------------------------------
    for (int e = tid; e < K_TOT; e += 1024) {
        int bkt = 0;
        #pragma unroll
        for (int l = 1; l < NUM_CLS; l++) bkt += (e >= soff[l]);
        const int pos = e - soff[bkt];
        const bool kp = (keep[bkt * KW_MAX + (pos >> 6)] >> (pos & 63)) & 1ull;
        const float f = kp ? 1.0f : 0.0f;
        const int rank = sidx[e];
        const float4 bb = bbx[e];
        const size_t o = ((size_t)b * K_TOT + rank) * 5;
        out[o + 0] = bb.x * f;
        out[o + 1] = bb.y * f;
        out[o + 2] = bb.z * f;
        out[o + 3] = bb.w * f;
        out[o + 4] = bsc[e] * f;
    }
}

// =============================================================================
extern "C" void kernel_launch(void* const* d_in, const int* in_sizes, int n_in,
                              void* d_out, int out_size) {
    const float* boxes   = (const float*)d_in[0];
    const float* scores  = (const float*)d_in[1];
    const int*   labels  = (const int*)  d_in[2];
    const float* weights = (const float*)d_in[3];
    float*       out     = (float*)d_out;

    static int smem_set = 0;
    if (!smem_set) {
        cudaFuncSetAttribute(k_all, cudaFuncAttributeMaxDynamicSharedMemorySize,
                             SMEM_TOTAL);
        smem_set = 1;
    }
    k_all<<<B_IMG, 1024, SMEM_TOTAL>>>(boxes, scores, labels, weights, out);
}

// round 9
// speedup vs baseline: 2.1159x; 2.1159x over previous
#include <cuda_runtime.h>
#include <cuda_bf16.h>
#include <cstdint>

typedef unsigned long long ull;

#define M_MODELS 3
#define B_IMG    16
#define N_BOX    512
#define K_TOT    (M_MODELS * N_BOX)   // 1536
#define PAD      2048
#define NUM_CLS  12
#define CAP      256                  // fast-path bucket capacity
#define W_MAX    4                    // CAP/64 mask words per row

// ---------------- device scratch (bucket-ordered, written by k_sort) ----------
__device__ float4 g_bbx [B_IMG * K_TOT];   // boxes, bucket order
__device__ float  g_bsc [B_IMG * K_TOT];   // weighted scores, bucket order
__device__ short  g_rank[B_IMG * K_TOT];   // bucket pos -> sorted rank
__device__ int    g_boff[B_IMG * NUM_CLS];
__device__ int    g_bcnt[B_IMG * NUM_CLS];

__device__ __forceinline__ void cswap(ull& x, ull& y, bool up) {
    if ((x > y) == up) { ull t = x; x = y; y = t; }
}

__device__ __forceinline__ ull shfl_stage(ull v, int e, unsigned j, unsigned ks) {
    const ull  o     = __shfl_xor_sync(0xffffffffu, v, j);
    const bool up    = ((e & ks) == 0);
    const bool lower = ((e & j) == 0);
    return ((v < o) == (lower == up)) ? v : o;
}

// division-free exact IoU>0.5 test: 0.5*d is exact in fp32
__device__ __forceinline__ bool iou_gt(const float4 bi, const float ai,
                                       const float4 bj, const float aj) {
    const float iw = fmaxf(fminf(bi.z, bj.z) - fmaxf(bi.x, bj.x), 0.0f);
    const float ih = fmaxf(fminf(bi.w, bj.w) - fmaxf(bi.y, bj.y), 0.0f);
    const float inter = iw * ih;
    const float uni   = ai + aj - inter;
    return inter > 0.5f * fmaxf(uni, 1e-9f);
}

// =============================================================================
// K1: sort (score desc, idx asc) + class compaction + bucket-ordered scatter.
// Everything k_nms needs is written contiguously per (image,class) so k_nms
// has zero dependent gathers.
// =============================================================================
__global__ __launch_bounds__(1024)
void k_sort(const float* __restrict__ boxes, const float* __restrict__ scores,
            const int* __restrict__ labels, const float* __restrict__ weights) {
    extern __shared__ char dyn[];
    ull*    key  = (ull*)dyn;                    // 16384 B
    float4* sbox = (float4*)(dyn + PAD * 8);     // 24576 B (sorted boxes)
    __shared__ short slab[K_TOT];
    __shared__ short sidx[K_TOT];                // bucket pos -> rank
    __shared__ int   soff[NUM_CLS], scnt[NUM_CLS];

    const int b    = blockIdx.x;
    const int tid  = threadIdx.x;
    const int warp = tid >> 5, lane = tid & 31;
    const int eA   = (warp << 6) | lane;
    const int eB   = eA | 32;

    const float w0 = weights[0], w1 = weights[1], w2 = weights[2];

    // ---- phase 1: hybrid bitonic sort ----
    auto mkkey = [&](int s) -> ull {
        if (s >= K_TOT) return ~0ull;
        const int m = s >> 9, n = s & (N_BOX - 1);
        const float wm = (m == 0) ? w0 : ((m == 1) ? w1 : w2);
        const float sc = scores[(m * B_IMG + b) * N_BOX + n] * wm;
        return ((ull)(~__float_as_uint(sc)) << 32) | (unsigned)s;
    };
    ull a = mkkey(eA);
    ull c = mkkey(eB);

    #pragma unroll
    for (int kb = 1; kb <= 6; kb++) {
        const unsigned ks = 1u << kb;
        if (ks == 64) cswap(a, c, ((eA & 64) == 0));
        const unsigned jstart = (ks == 64) ? 16u : (ks >> 1);
        #pragma unroll
        for (unsigned j = jstart; j >= 1; j >>= 1) {
            a = shfl_stage(a, eA, j, ks);
            c = shfl_stage(c, eB, j, ks);
        }
    }
    key[eA] = a;
    key[eB] = c;

    #pragma unroll
    for (unsigned ks = 128; ks <= PAD; ks <<= 1) {
        for (unsigned j = ks >> 1; j >= 64; j >>= 1) {
            __syncthreads();
            const unsigned i = ((tid & ~(j - 1)) << 1) | (tid & (j - 1));
            const unsigned p = i | j;
            const ull x = key[i];
            const ull y = key[p];
            const bool up = ((i & ks) == 0);
            if ((x > y) == up) { key[i] = y; key[p] = x; }
        }
        __syncthreads();
        a = key[eA]; c = key[eB];
        cswap(a, c, ((eA & ks) == 0));
        #pragma unroll
        for (unsigned j = 16; j >= 1; j >>= 1) {
            a = shfl_stage(a, eA, j, ks);
            c = shfl_stage(c, eB, j, ks);
        }
        key[eA] = a; key[eB] = c;
    }
    __syncthreads();

    // ---- phase 2: gather sorted boxes + labels into smem ----
    for (int r = tid; r < K_TOT; r += 1024) {
        const int e = (int)(key[r] & 0xffffffffu);
        const int m = e >> 9, n = e & (N_BOX - 1);
        const size_t src = ((size_t)m * B_IMG + b) * N_BOX + n;
        sbox[r] = *(const float4*)&boxes[src * 4];
        slab[r] = (short)labels[src];
    }
    __syncthreads();

    // ---- phase 3: stable per-class compaction (warp l = class l) ----
    if (warp < NUM_CLS) {
        int cnt = 0;
        for (int base = 0; base < K_TOT; base += 32) {
            const bool m = (slab[base + lane] == (short)warp);
            cnt += __popc(__ballot_sync(0xffffffffu, m));
        }
        if (lane == 0) scnt[warp] = cnt;
    }
    __syncthreads();
    if (tid == 0) {
        int acc = 0;
        #pragma unroll
        for (int l = 0; l < NUM_CLS; l++) { soff[l] = acc; acc += scnt[l]; }
    }
    __syncthreads();
    if (warp < NUM_CLS) {
        const int off = soff[warp];
        int cnt = 0;
        for (int base = 0; base < K_TOT; base += 32) {
            const bool m = (slab[base + lane] == (short)warp);
            const unsigned bal = __ballot_sync(0xffffffffu, m);
            if (m) {
                const int pos = cnt + __popc(bal & ((1u << lane) - 1u));
                sidx[off + pos] = (short)(base + lane);
            }
            cnt += __popc(bal);
        }
        if (lane == 0) {
            g_boff[b * NUM_CLS + warp] = off;
            g_bcnt[b * NUM_CLS + warp] = cnt;
        }
    }
    __syncthreads();

    // ---- phase 4: bucket-ordered scatter to global (coalesced writes) ----
    for (int e = tid; e < K_TOT; e += 1024) {
        const int rank = sidx[e];
        const size_t dst = (size_t)b * K_TOT + e;
        g_bbx [dst] = sbox[rank];
        g_bsc [dst] = __uint_as_float(~(unsigned)(key[rank] >> 32));
        g_rank[dst] = (short)rank;
    }
}

// =============================================================================
// K2: per-(image,class) NMS. Coalesced bucket load -> 8-warp matrix build with
// rowNZ tracking -> single-thread register-resident sparse greedy chase ->
// direct output of this bucket's rows.
// =============================================================================
__global__ __launch_bounds__(256)
void k_nms(float* __restrict__ out) {
    __shared__ float4 bx[CAP];
    __shared__ float  ar[CAP];
    __shared__ ull    smask[CAP * W_MAX];     // 8 KB
    __shared__ ull    rownz[W_MAX];
    __shared__ ull    keepw[W_MAX];

    const int img  = blockIdx.x / NUM_CLS;
    const int cls  = blockIdx.x % NUM_CLS;
    const int tid  = threadIdx.x;
    const int warp = tid >> 5, lane = tid & 31;

    const int off = g_boff[img * NUM_CLS + cls];
    const int cnt = g_bcnt[img * NUM_CLS + cls];
    if (cnt == 0) return;

    const size_t gbase = (size_t)img * K_TOT + off;

    if (cnt <= CAP) {
        if (tid < W_MAX) { rownz[tid] = 0ull; keepw[tid] = ~0ull; }
        for (int m = tid; m < cnt; m += 256) {
            const float4 bb = g_bbx[gbase + m];
            bx[m] = bb;
            ar[m] = (bb.z - bb.x) * (bb.w - bb.y);
        }
        __syncthreads();

        const int W = (cnt + 63) >> 6;
        // ---- matrix build: rows striped over 8 warps ----
        for (int r = warp; r < cnt; r += 8) {
            const float4 bi = bx[r];
            const float  ai = ar[r];
            ull nz = 0ull;
            for (int w = r >> 6; w < W; w++) {
                const int j0 = w * 64 + lane;
                const int j1 = j0 + 32;
                bool p0 = false, p1 = false;
                if (j0 > r && j0 < cnt) p0 = iou_gt(bi, ai, bx[j0], ar[j0]);
                if (j1 > r && j1 < cnt) p1 = iou_gt(bi, ai, bx[j1], ar[j1]);
                const unsigned lo = __ballot_sync(0xffffffffu, p0);
                const unsigned hi = __ballot_sync(0xffffffffu, p1);
                const ull mword = ((ull)hi << 32) | lo;
                if (lane == 0) smask[r * W_MAX + w] = mword;
                nz |= mword;
            }
            if (lane == 0 && nz)
                atomicOr(&rownz[r >> 6], 1ull << (r & 63));
        }
        __syncthreads();

        // ---- sparse greedy chase, single thread, removed[] in registers ----
        if (tid == 0) {
            ull rem0 = 0, rem1 = 0, rem2 = 0, rem3 = 0;
            #pragma unroll
            for (int w = 0; w < W_MAX; w++) {
                if (w >= W) break;
                ull act = rownz[w];
                ull rw  = (w == 0) ? rem0 : (w == 1) ? rem1 : (w == 2) ? rem2 : rem3;
                act &= ~rw;
                while (act) {
                    const int bit = __ffsll((long long)act) - 1;
                    act &= act - 1;
                    if (!((rw >> bit) & 1ull)) {
                        const int i = w * 64 + bit;
                        const ull* row = &smask[i * W_MAX];
                        // OR row words w..W-1 into removed
                        if (w <= 0) rem0 |= row[0];
                        if (w <= 1 && W > 1) rem1 |= row[1];
                        if (w <= 2 && W > 2) rem2 |= row[2];
                        if (w <= 3 && W > 3) rem3 |= row[3];
                        rw = (w == 0) ? rem0 : (w == 1) ? rem1 : (w == 2) ? rem2 : rem3;
                        act &= ~rw;
                    }
                }
            }
            keepw[0] = ~rem0; keepw[1] = ~rem1; keepw[2] = ~rem2; keepw[3] = ~rem3;
        }
        __syncthreads();

        // ---- output this bucket's rows ----
        for (int m = tid; m < cnt; m += 256) {
            const bool kp = (keepw[m >> 6] >> (m & 63)) & 1ull;
            const float f = kp ? 1.0f : 0.0f;
            const int rank = g_rank[gbase + m];
            const float4 bb = bx[m];
            const size_t o = ((size_t)img * K_TOT + rank) * 5;
            out[o + 0] = bb.x * f;
            out[o + 1] = bb.y * f;
            out[o + 2] = bb.z * f;
            out[o + 3] = bb.w * f;
            out[o + 4] = g_bsc[gbase + m] * f;
        }
    } else {
        // ---- fallback (cnt > CAP): warp-serial kept-list from global ----
        __shared__ short kidx[K_TOT];
        if (warp == 0) {
            int nk = 0;
            for (int cix = 0; cix < cnt; cix++) {
                const float4 bc = g_bbx[gbase + cix];
                const float  ac = (bc.z - bc.x) * (bc.w - bc.y);
                bool sup = false;
                for (int k = lane; k < nk; k += 32) {
                    const float4 bk = g_bbx[gbase + kidx[k]];
                    const float  ak = (bk.z - bk.x) * (bk.w - bk.y);
                    if (iou_gt(bc, ac, bk, ak)) { sup = true; break; }
                }
                sup = (__ballot_sync(0xffffffffu, sup) != 0u);
                if (!sup) {
                    if (lane == 0) kidx[nk] = (short)cix;
                    nk++;
                }
                if (lane == 0) {
                    const float f = sup ? 0.0f : 1.0f;
                    const int rank = g_rank[gbase + cix];
                    const size_t o = ((size_t)img * K_TOT + rank) * 5;
                    out[o + 0] = bc.x * f;
                    out[o + 1] = bc.y * f;
                    out[o + 2] = bc.z * f;
                    out[o + 3] = bc.w * f;
                    out[o + 4] = g_bsc[gbase + cix] * f;
                }
                __syncwarp();
            }
        }
    }
}

// =============================================================================
extern "C" void kernel_launch(void* const* d_in, const int* in_sizes, int n_in,
                              void* d_out, int out_size) {
    const float* boxes   = (const float*)d_in[0];
    const float* scores  = (const float*)d_in[1];
    const int*   labels  = (const int*)  d_in[2];
    const float* weights = (const float*)d_in[3];
    float*       out     = (float*)d_out;

    k_sort<<<B_IMG, 1024, PAD * 8 + K_TOT * 16>>>(boxes, scores, labels, weights);
    k_nms <<<B_IMG * NUM_CLS, 256>>>(out);
}